// round 1
// baseline (speedup 1.0000x reference)
#include <cuda_runtime.h>
#include <cuda_bf16.h>

// GAT layer: N=100000 nodes, E=1600000 edges, F=128 in-feat, H=64 hidden.
// Pipeline:
//   K0: detect edge_index dtype (int64 vs int32) -> g_is64
//   K1: h0 = x @ fc_w^T            (tiled fp32 GEMM, 128x64 tile)
//   K2: s_src/s_dst per node, zero h_sum and out
//   K3: per-edge e -> leakyrelu -> exp -> h_e, atomic h_sum[src]
//   K4: alpha = h_e/h_sum[src]; out[src] += adj*alpha*h0[dst]  (red.v4.f32)

#define NN 100000
#define EE 1600000
#define FF 128
#define HH 64
#define LEAKY 0.05f

__device__ float g_h0[NN * HH];     // 25.6 MB scratch
__device__ float g_ssrc[NN];
__device__ float g_sdst[NN];
__device__ float g_hsum[NN];
__device__ float g_he[EE];          // 6.4 MB scratch
__device__ int   g_is64;

// ---------------------------------------------------------------------------
// K0: dtype detection. If the first 64 int64-interpreted values are all valid
// node ids, the buffer is int64; otherwise it is int32 (JAX x64-off case).
// ---------------------------------------------------------------------------
__global__ void k_detect(const void* __restrict__ ei) {
    int lane = threadIdx.x;
    const long long* p = (const long long*)ei;
    bool ok = true;
    long long v0 = p[lane];
    long long v1 = p[lane + 32];
    if (v0 < 0 || v0 >= NN) ok = false;
    if (v1 < 0 || v1 >= NN) ok = false;
    unsigned m = __ballot_sync(0xFFFFFFFFu, ok);
    if (lane == 0) g_is64 = (m == 0xFFFFFFFFu) ? 1 : 0;
}

__device__ __forceinline__ int load_idx(const void* ei, int which, int e) {
    if (g_is64) {
        return (int)((const long long*)ei)[(long long)which * EE + e];
    } else {
        return ((const int*)ei)[which * EE + e];
    }
}

// ---------------------------------------------------------------------------
// K1: h0[N,64] = x[N,128] @ W^T  (W is [64,128] row-major)
// Block tile: 128 nodes x 64 hidden, KC=32. 256 threads, 8x4 microtile.
// ---------------------------------------------------------------------------
__global__ __launch_bounds__(256) void k_gemm(const float* __restrict__ x,
                                              const float* __restrict__ w) {
    __shared__ float As[128][33];   // [m][k], pad 1
    __shared__ float Bs[32][68];    // [k][h], pad to 68 (16B-aligned rows)

    const int tid = threadIdx.x;
    const int tx = tid & 15;        // hidden group: h = tx*4 .. tx*4+3
    const int ty = tid >> 4;        // node group:  m = ty*8 .. ty*8+7
    const int m0 = blockIdx.x * 128;

    float acc[8][4];
#pragma unroll
    for (int i = 0; i < 8; i++)
#pragma unroll
        for (int j = 0; j < 4; j++) acc[i][j] = 0.f;

    for (int kc = 0; kc < FF; kc += 32) {
        // load A tile: 128 x 32 floats
        {
            int k4 = tid & 7;           // float4 index within 32-k chunk
            int rb = tid >> 3;          // 0..31
#pragma unroll
            for (int r = 0; r < 4; r++) {
                int m = rb + r * 32;
                int gm = m0 + m;
                float4 v = make_float4(0.f, 0.f, 0.f, 0.f);
                if (gm < NN) v = *(const float4*)&x[(long long)gm * FF + kc + k4 * 4];
                As[m][k4 * 4 + 0] = v.x;
                As[m][k4 * 4 + 1] = v.y;
                As[m][k4 * 4 + 2] = v.z;
                As[m][k4 * 4 + 3] = v.w;
            }
        }
        // load B tile: W[h][kc..kc+31] -> Bs[k][h]
        {
            int h = tid >> 2;           // 0..63
            int kq = tid & 3;
#pragma unroll
            for (int j = 0; j < 2; j++) {
                int kk = kq * 4 + j * 16;
                float4 v = *(const float4*)&w[h * FF + kc + kk];
                Bs[kk + 0][h] = v.x;
                Bs[kk + 1][h] = v.y;
                Bs[kk + 2][h] = v.z;
                Bs[kk + 3][h] = v.w;
            }
        }
        __syncthreads();
#pragma unroll
        for (int k = 0; k < 32; k++) {
            float4 b = *(const float4*)&Bs[k][tx * 4];
            float a[8];
#pragma unroll
            for (int i = 0; i < 8; i++) a[i] = As[ty * 8 + i][k];
#pragma unroll
            for (int i = 0; i < 8; i++) {
                acc[i][0] += a[i] * b.x;
                acc[i][1] += a[i] * b.y;
                acc[i][2] += a[i] * b.z;
                acc[i][3] += a[i] * b.w;
            }
        }
        __syncthreads();
    }

#pragma unroll
    for (int i = 0; i < 8; i++) {
        int gm = m0 + ty * 8 + i;
        if (gm < NN) {
            float4 v = make_float4(acc[i][0], acc[i][1], acc[i][2], acc[i][3]);
            *(float4*)&g_h0[(long long)gm * HH + tx * 4] = v;
        }
    }
}

// ---------------------------------------------------------------------------
// K2: per-node s_src/s_dst, zero h_sum and out rows. One warp per node.
// ---------------------------------------------------------------------------
__global__ __launch_bounds__(256) void k_node(const float* __restrict__ aw,
                                              float* __restrict__ out) {
    int warp = (blockIdx.x * blockDim.x + threadIdx.x) >> 5;
    int lane = threadIdx.x & 31;
    if (warp >= NN) return;
    float v0 = g_h0[warp * HH + lane];
    float v1 = g_h0[warp * HH + 32 + lane];
    float ss = v0 * __ldg(&aw[lane])      + v1 * __ldg(&aw[lane + 32]);
    float sd = v0 * __ldg(&aw[64 + lane]) + v1 * __ldg(&aw[96 + lane]);
#pragma unroll
    for (int o = 16; o > 0; o >>= 1) {
        ss += __shfl_xor_sync(0xFFFFFFFFu, ss, o);
        sd += __shfl_xor_sync(0xFFFFFFFFu, sd, o);
    }
    if (lane == 0) {
        g_ssrc[warp] = ss;
        g_sdst[warp] = sd;
        g_hsum[warp] = 0.f;
    }
    out[warp * HH + lane] = 0.f;
    out[warp * HH + 32 + lane] = 0.f;
}

// ---------------------------------------------------------------------------
// K3: per-edge attention logit -> exp, accumulate softmax denominator.
// ---------------------------------------------------------------------------
__global__ __launch_bounds__(256) void k_edge1(const void* __restrict__ ei,
                                               const float* __restrict__ ab) {
    int e = blockIdx.x * blockDim.x + threadIdx.x;
    if (e >= EE) return;
    int src = load_idx(ei, 0, e);
    int dst = load_idx(ei, 1, e);
    float v = g_ssrc[src] + g_sdst[dst] + ab[0];
    v = (v >= 0.f) ? v : LEAKY * v;
    float h = expf(v);
    g_he[e] = h;
    atomicAdd(&g_hsum[src], h);
}

// ---------------------------------------------------------------------------
// K4: alpha + scatter-accumulate. 16 lanes per edge, one float4 per lane.
// ---------------------------------------------------------------------------
__global__ __launch_bounds__(256) void k_edge2(const void* __restrict__ ei,
                                               const float* __restrict__ adj,
                                               float* __restrict__ out,
                                               float* __restrict__ alpha_out) {
    long long t = (long long)blockIdx.x * blockDim.x + threadIdx.x;
    int e = (int)(t >> 4);
    int ln = (int)(t & 15);
    if (e >= EE) return;
    int src = load_idx(ei, 0, e);
    int dst = load_idx(ei, 1, e);
    float alpha = g_he[e] / g_hsum[src];
    if (ln == 0 && alpha_out) alpha_out[e] = alpha;
    float val = adj[e] * alpha;
    float4 hv = *(const float4*)&g_h0[(long long)dst * HH + ln * 4];
    float* p = &out[(long long)src * HH + ln * 4];
    asm volatile("red.global.add.v4.f32 [%0], {%1, %2, %3, %4};"
                 :: "l"(p), "f"(val * hv.x), "f"(val * hv.y),
                    "f"(val * hv.z), "f"(val * hv.w)
                 : "memory");
}

// ---------------------------------------------------------------------------
extern "C" void kernel_launch(void* const* d_in, const int* in_sizes, int n_in,
                              void* d_out, int out_size) {
    const float* x    = (const float*)d_in[0];
    const void*  ei   = d_in[1];
    const float* adj  = (const float*)d_in[2];
    const float* fc_w = (const float*)d_in[3];
    const float* a_w  = (const float*)d_in[4];
    const float* a_b  = (const float*)d_in[5];
    float* out = (float*)d_out;
    float* alpha_out = (out_size >= NN * HH + EE) ? (out + NN * HH) : nullptr;

    k_detect<<<1, 32>>>(ei);
    k_gemm<<<(NN + 127) / 128, 256>>>(x, fc_w);
    k_node<<<(NN * 32 + 255) / 256, 256>>>(a_w, out);
    k_edge1<<<(EE + 255) / 256, 256>>>(ei, a_b);
    {
        long long threads = (long long)EE * 16;
        int blocks = (int)((threads + 255) / 256);
        k_edge2<<<blocks, 256>>>(ei, adj, out, alpha_out);
    }
}

// round 3
// speedup vs baseline: 1.2009x; 1.2009x over previous
#include <cuda_runtime.h>
#include <cuda_bf16.h>

// GAT layer: N=100000 nodes, E=1600000 edges, F=128 in-feat, H=64 hidden.
// Pipeline (all graph-capturable, no allocation):
//   K0 detect : edge_index dtype (int64 vs int32) -> g_is64
//   K1 gemm   : h0 = x @ fc_w^T        (tiled fp32 GEMM)
//   K2 node   : s_src/s_dst per node; zero hsum/deg
//   K3 edge1  : he=exp(leaky(...)); atomic hsum[src]; atomic deg[src]
//   K4 scanA/B/C : exclusive prefix sum of deg -> start, cursor
//   K5 scatter: alpha; pair[pos]=(dst, adj*alpha) at sorted position
//   K6 gather : per-node register accumulation, single write (no atomics)

#define NN 100000
#define EE 1600000
#define FF 128
#define HH 64
#define LEAKY 0.05f
#define SCAN_T 1024
#define NBLK ((NN + SCAN_T - 1) / SCAN_T)   // 98

__device__ float g_h0[NN * HH];     // 25.6 MB
__device__ float g_ssrc[NN];
__device__ float g_sdst[NN];
__device__ float g_hsum[NN];
__device__ float g_he[EE];          // 6.4 MB
__device__ int   g_deg[NN];
__device__ int   g_start[NN];
__device__ int   g_cursor[NN];
__device__ int   g_bsum[NBLK];
__device__ int   g_boff[NBLK];
__device__ int2  g_pair[EE];        // 12.8 MB (dst, val-as-int)
__device__ int   g_is64;

// ---------------------------------------------------------------------------
__global__ void k_detect(const void* __restrict__ ei) {
    int lane = threadIdx.x;
    const long long* p = (const long long*)ei;
    bool ok = true;
    long long v0 = p[lane];
    long long v1 = p[lane + 32];
    if (v0 < 0 || v0 >= NN) ok = false;
    if (v1 < 0 || v1 >= NN) ok = false;
    unsigned m = __ballot_sync(0xFFFFFFFFu, ok);
    if (lane == 0) g_is64 = (m == 0xFFFFFFFFu) ? 1 : 0;
}

__device__ __forceinline__ int load_idx(const void* ei, int which, int e) {
    if (g_is64) return (int)((const long long*)ei)[(long long)which * EE + e];
    return ((const int*)ei)[which * EE + e];
}

// ---------------------------------------------------------------------------
// K1: h0[N,64] = x[N,128] @ W^T  (W row-major [64,128])
// ---------------------------------------------------------------------------
__global__ __launch_bounds__(256) void k_gemm(const float* __restrict__ x,
                                              const float* __restrict__ w) {
    __shared__ float As[128][33];
    __shared__ float Bs[32][68];

    const int tid = threadIdx.x;
    const int tx = tid & 15;
    const int ty = tid >> 4;
    const int m0 = blockIdx.x * 128;

    float acc[8][4];
#pragma unroll
    for (int i = 0; i < 8; i++)
#pragma unroll
        for (int j = 0; j < 4; j++) acc[i][j] = 0.f;

    for (int kc = 0; kc < FF; kc += 32) {
        {
            int k4 = tid & 7;
            int rb = tid >> 3;
#pragma unroll
            for (int r = 0; r < 4; r++) {
                int m = rb + r * 32;
                int gm = m0 + m;
                float4 v = make_float4(0.f, 0.f, 0.f, 0.f);
                if (gm < NN) v = *(const float4*)&x[(long long)gm * FF + kc + k4 * 4];
                As[m][k4 * 4 + 0] = v.x;
                As[m][k4 * 4 + 1] = v.y;
                As[m][k4 * 4 + 2] = v.z;
                As[m][k4 * 4 + 3] = v.w;
            }
        }
        {
            int h = tid >> 2;
            int kq = tid & 3;
#pragma unroll
            for (int j = 0; j < 2; j++) {
                int kk = kq * 4 + j * 16;
                float4 v = *(const float4*)&w[h * FF + kc + kk];
                Bs[kk + 0][h] = v.x;
                Bs[kk + 1][h] = v.y;
                Bs[kk + 2][h] = v.z;
                Bs[kk + 3][h] = v.w;
            }
        }
        __syncthreads();
#pragma unroll
        for (int k = 0; k < 32; k++) {
            float4 b = *(const float4*)&Bs[k][tx * 4];
            float a[8];
#pragma unroll
            for (int i = 0; i < 8; i++) a[i] = As[ty * 8 + i][k];
#pragma unroll
            for (int i = 0; i < 8; i++) {
                acc[i][0] += a[i] * b.x;
                acc[i][1] += a[i] * b.y;
                acc[i][2] += a[i] * b.z;
                acc[i][3] += a[i] * b.w;
            }
        }
        __syncthreads();
    }
#pragma unroll
    for (int i = 0; i < 8; i++) {
        int gm = m0 + ty * 8 + i;
        if (gm < NN)
            *(float4*)&g_h0[(long long)gm * HH + tx * 4] =
                make_float4(acc[i][0], acc[i][1], acc[i][2], acc[i][3]);
    }
}

// ---------------------------------------------------------------------------
// K2: per-node s_src/s_dst; zero hsum + deg. One warp per node.
// ---------------------------------------------------------------------------
__global__ __launch_bounds__(256) void k_node(const float* __restrict__ aw) {
    int warp = (blockIdx.x * blockDim.x + threadIdx.x) >> 5;
    int lane = threadIdx.x & 31;
    if (warp >= NN) return;
    float v0 = g_h0[warp * HH + lane];
    float v1 = g_h0[warp * HH + 32 + lane];
    float ss = v0 * __ldg(&aw[lane])      + v1 * __ldg(&aw[lane + 32]);
    float sd = v0 * __ldg(&aw[64 + lane]) + v1 * __ldg(&aw[96 + lane]);
#pragma unroll
    for (int o = 16; o > 0; o >>= 1) {
        ss += __shfl_xor_sync(0xFFFFFFFFu, ss, o);
        sd += __shfl_xor_sync(0xFFFFFFFFu, sd, o);
    }
    if (lane == 0) {
        g_ssrc[warp] = ss;
        g_sdst[warp] = sd;
        g_hsum[warp] = 0.f;
        g_deg[warp]  = 0;
    }
}

// ---------------------------------------------------------------------------
// K3: per-edge exp(leaky(logit)); accumulate softmax denominator + degree.
// ---------------------------------------------------------------------------
__global__ __launch_bounds__(256) void k_edge1(const void* __restrict__ ei,
                                               const float* __restrict__ ab) {
    int e = blockIdx.x * blockDim.x + threadIdx.x;
    if (e >= EE) return;
    int src = load_idx(ei, 0, e);
    int dst = load_idx(ei, 1, e);
    float v = g_ssrc[src] + g_sdst[dst] + ab[0];
    v = (v >= 0.f) ? v : LEAKY * v;
    float h = expf(v);
    g_he[e] = h;
    atomicAdd(&g_hsum[src], h);
    atomicAdd(&g_deg[src], 1);
}

// ---------------------------------------------------------------------------
// K4: exclusive scan of deg (3 small kernels)
// ---------------------------------------------------------------------------
__global__ __launch_bounds__(SCAN_T) void k_scanA() {
    __shared__ int s[SCAN_T];
    int t = threadIdx.x;
    int i = blockIdx.x * SCAN_T + t;
    int v = (i < NN) ? g_deg[i] : 0;
    s[t] = v;
    __syncthreads();
#pragma unroll
    for (int o = 1; o < SCAN_T; o <<= 1) {
        int x = (t >= o) ? s[t - o] : 0;
        __syncthreads();
        s[t] += x;
        __syncthreads();
    }
    if (i < NN) g_start[i] = s[t] - v;
    if (t == SCAN_T - 1) g_bsum[blockIdx.x] = s[t];
}

__global__ __launch_bounds__(128) void k_scanB() {
    __shared__ int s[128];
    int t = threadIdx.x;
    int v = (t < NBLK) ? g_bsum[t] : 0;
    s[t] = v;
    __syncthreads();
#pragma unroll
    for (int o = 1; o < 128; o <<= 1) {
        int x = (t >= o) ? s[t - o] : 0;
        __syncthreads();
        s[t] += x;
        __syncthreads();
    }
    if (t < NBLK) g_boff[t] = s[t] - v;
}

__global__ __launch_bounds__(256) void k_scanC() {
    int i = blockIdx.x * blockDim.x + threadIdx.x;
    if (i >= NN) return;
    int st = g_start[i] + g_boff[i >> 10];
    g_start[i] = st;
    g_cursor[i] = st;
}

// ---------------------------------------------------------------------------
// K5: scatter edges into CSR slots; emit alpha.
// ---------------------------------------------------------------------------
__global__ __launch_bounds__(256) void k_scatter(const void* __restrict__ ei,
                                                 const float* __restrict__ adj,
                                                 float* __restrict__ alpha_out) {
    int e = blockIdx.x * blockDim.x + threadIdx.x;
    if (e >= EE) return;
    int src = load_idx(ei, 0, e);
    int dst = load_idx(ei, 1, e);
    float alpha = g_he[e] / g_hsum[src];
    if (alpha_out) alpha_out[e] = alpha;
    float a = adj[e] * alpha;
    int pos = atomicAdd(&g_cursor[src], 1);
    g_pair[pos] = make_int2(dst, __float_as_int(a));
}

// ---------------------------------------------------------------------------
// K6: per-node gather-accumulate. One warp per node, no atomics.
// Each lane owns columns lane and lane+32.
// ---------------------------------------------------------------------------
__global__ __launch_bounds__(256) void k_gather(float* __restrict__ out) {
    int warp = (blockIdx.x * blockDim.x + threadIdx.x) >> 5;
    int lane = threadIdx.x & 31;
    if (warp >= NN) return;
    int beg = g_start[warp];
    int cnt = g_deg[warp];
    float a0 = 0.f, a1 = 0.f;
    for (int b = 0; b < cnt; b += 32) {
        int n = min(32, cnt - b);
        int2 pr = make_int2(0, 0);
        if (lane < n) pr = g_pair[beg + b + lane];
        int j = 0;
        for (; j + 4 <= n; j += 4) {
            int d0 = __shfl_sync(0xFFFFFFFFu, pr.x, j + 0);
            int d1 = __shfl_sync(0xFFFFFFFFu, pr.x, j + 1);
            int d2 = __shfl_sync(0xFFFFFFFFu, pr.x, j + 2);
            int d3 = __shfl_sync(0xFFFFFFFFu, pr.x, j + 3);
            float v0 = __int_as_float(__shfl_sync(0xFFFFFFFFu, pr.y, j + 0));
            float v1 = __int_as_float(__shfl_sync(0xFFFFFFFFu, pr.y, j + 1));
            float v2 = __int_as_float(__shfl_sync(0xFFFFFFFFu, pr.y, j + 2));
            float v3 = __int_as_float(__shfl_sync(0xFFFFFFFFu, pr.y, j + 3));
            float h00 = __ldg(&g_h0[d0 * HH + lane]);
            float h01 = __ldg(&g_h0[d0 * HH + 32 + lane]);
            float h10 = __ldg(&g_h0[d1 * HH + lane]);
            float h11 = __ldg(&g_h0[d1 * HH + 32 + lane]);
            float h20 = __ldg(&g_h0[d2 * HH + lane]);
            float h21 = __ldg(&g_h0[d2 * HH + 32 + lane]);
            float h30 = __ldg(&g_h0[d3 * HH + lane]);
            float h31 = __ldg(&g_h0[d3 * HH + 32 + lane]);
            a0 += v0 * h00; a1 += v0 * h01;
            a0 += v1 * h10; a1 += v1 * h11;
            a0 += v2 * h20; a1 += v2 * h21;
            a0 += v3 * h30; a1 += v3 * h31;
        }
        for (; j < n; j++) {
            int d = __shfl_sync(0xFFFFFFFFu, pr.x, j);
            float v = __int_as_float(__shfl_sync(0xFFFFFFFFu, pr.y, j));
            a0 += v * __ldg(&g_h0[d * HH + lane]);
            a1 += v * __ldg(&g_h0[d * HH + 32 + lane]);
        }
    }
    out[warp * HH + lane] = a0;
    out[warp * HH + 32 + lane] = a1;
}

// ---------------------------------------------------------------------------
extern "C" void kernel_launch(void* const* d_in, const int* in_sizes, int n_in,
                              void* d_out, int out_size) {
    const float* x    = (const float*)d_in[0];
    const void*  ei   = d_in[1];
    const float* adj  = (const float*)d_in[2];
    const float* fc_w = (const float*)d_in[3];
    const float* a_w  = (const float*)d_in[4];
    const float* a_b  = (const float*)d_in[5];
    float* out = (float*)d_out;
    float* alpha_out = (out_size >= NN * HH + EE) ? (out + NN * HH) : nullptr;

    k_detect<<<1, 32>>>(ei);
    k_gemm<<<(NN + 127) / 128, 256>>>(x, fc_w);
    k_node<<<(NN * 32 + 255) / 256, 256>>>(a_w);
    k_edge1<<<(EE + 255) / 256, 256>>>(ei, a_b);
    k_scanA<<<NBLK, SCAN_T>>>();
    k_scanB<<<1, 128>>>();
    k_scanC<<<(NN + 255) / 256, 256>>>();
    k_scatter<<<(EE + 255) / 256, 256>>>(ei, adj, alpha_out);
    k_gather<<<(NN * 32 + 255) / 256, 256>>>(out);
}

// round 4
// speedup vs baseline: 1.2976x; 1.0805x over previous
#include <cuda_runtime.h>
#include <cuda_bf16.h>
#include <cuda_fp16.h>

// GAT layer: N=100000, E=1600000, F=128, H=64.
// Pipeline:
//   K0 detect : edge_index dtype (int64 vs int32) -> g_is64
//   K1 gemm   : h0(fp16) = x @ fc_w^T ; fused epilogue computes s_src/s_dst
//               from registers and zeroes hsum/deg
//   K2 edge1  : he=exp(leaky(ssrc+sdst+b)); atomic hsum/deg; compact int2(src,dst)
//   K3 scanA/B/C : exclusive prefix sum of deg -> start, cursor
//   K4 scatter: recompute alpha; pair[pos]=(dst, adj*alpha); alpha_out
//   K5 gather : per-node register accumulation over fp16 h0, no atomics

#define NN 100000
#define EE 1600000
#define FF 128
#define HH 64
#define LEAKY 0.05f
#define SCAN_T 1024
#define NBLK ((NN + SCAN_T - 1) / SCAN_T)   // 98

__device__ __half g_h0h[NN * HH];   // 12.8 MB (fp16 h0)
__device__ float g_ssrc[NN];
__device__ float g_sdst[NN];
__device__ float g_hsum[NN];
__device__ int   g_deg[NN];
__device__ int   g_start[NN];
__device__ int   g_cursor[NN];
__device__ int   g_bsum[NBLK];
__device__ int   g_boff[NBLK];
__device__ int2  g_sd[EE];          // 12.8 MB compact (src,dst)
__device__ int2  g_pair[EE];        // 12.8 MB (dst, adj*alpha)
__device__ int   g_is64;

// ---------------------------------------------------------------------------
__global__ void k_detect(const void* __restrict__ ei) {
    int lane = threadIdx.x;
    const long long* p = (const long long*)ei;
    bool ok = true;
    long long v0 = p[lane];
    long long v1 = p[lane + 32];
    if (v0 < 0 || v0 >= NN) ok = false;
    if (v1 < 0 || v1 >= NN) ok = false;
    unsigned m = __ballot_sync(0xFFFFFFFFu, ok);
    if (lane == 0) g_is64 = (m == 0xFFFFFFFFu) ? 1 : 0;
}

__device__ __forceinline__ int load_idx(const void* ei, int which, int e) {
    if (g_is64) return (int)((const long long*)ei)[(long long)which * EE + e];
    return ((const int*)ei)[which * EE + e];
}

// ---------------------------------------------------------------------------
// K1: h0[N,64] = x[N,128] @ W^T, fp16 store + fused s_src/s_dst epilogue.
// Block tile 128 x 64, 256 threads, each thread: 8 nodes x 4 cols.
// tid = ty*16+tx : tx in [0,16) -> cols tx*4..tx*4+3 ; ty in [0,16) -> rows.
// ---------------------------------------------------------------------------
__global__ __launch_bounds__(256) void k_gemm(const float* __restrict__ x,
                                              const float* __restrict__ w,
                                              const float* __restrict__ aw) {
    __shared__ float As[128][33];
    __shared__ float Bs[32][68];

    const int tid = threadIdx.x;
    const int tx = tid & 15;
    const int ty = tid >> 4;
    const int m0 = blockIdx.x * 128;

    float acc[8][4];
#pragma unroll
    for (int i = 0; i < 8; i++)
#pragma unroll
        for (int j = 0; j < 4; j++) acc[i][j] = 0.f;

    for (int kc = 0; kc < FF; kc += 32) {
        {
            int k4 = tid & 7;
            int rb = tid >> 3;
#pragma unroll
            for (int r = 0; r < 4; r++) {
                int m = rb + r * 32;
                int gm = m0 + m;
                float4 v = make_float4(0.f, 0.f, 0.f, 0.f);
                if (gm < NN) v = *(const float4*)&x[(long long)gm * FF + kc + k4 * 4];
                As[m][k4 * 4 + 0] = v.x;
                As[m][k4 * 4 + 1] = v.y;
                As[m][k4 * 4 + 2] = v.z;
                As[m][k4 * 4 + 3] = v.w;
            }
        }
        {
            int h = tid >> 2;
            int kq = tid & 3;
#pragma unroll
            for (int j = 0; j < 2; j++) {
                int kk = kq * 4 + j * 16;
                float4 v = *(const float4*)&w[h * FF + kc + kk];
                Bs[kk + 0][h] = v.x;
                Bs[kk + 1][h] = v.y;
                Bs[kk + 2][h] = v.z;
                Bs[kk + 3][h] = v.w;
            }
        }
        __syncthreads();
#pragma unroll
        for (int k = 0; k < 32; k++) {
            float4 b = *(const float4*)&Bs[k][tx * 4];
            float a[8];
#pragma unroll
            for (int i = 0; i < 8; i++) a[i] = As[ty * 8 + i][k];
#pragma unroll
            for (int i = 0; i < 8; i++) {
                acc[i][0] += a[i] * b.x;
                acc[i][1] += a[i] * b.y;
                acc[i][2] += a[i] * b.z;
                acc[i][3] += a[i] * b.w;
            }
        }
        __syncthreads();
    }

    // attention weights for this thread's 4 columns
    float aw0 = __ldg(&aw[tx * 4 + 0]), aw1 = __ldg(&aw[tx * 4 + 1]);
    float aw2 = __ldg(&aw[tx * 4 + 2]), aw3 = __ldg(&aw[tx * 4 + 3]);
    float bw0 = __ldg(&aw[64 + tx * 4 + 0]), bw1 = __ldg(&aw[64 + tx * 4 + 1]);
    float bw2 = __ldg(&aw[64 + tx * 4 + 2]), bw3 = __ldg(&aw[64 + tx * 4 + 3]);

#pragma unroll
    for (int i = 0; i < 8; i++) {
        int gm = m0 + ty * 8 + i;
        // fp16 store of h0 row fragment
        if (gm < NN) {
            __half2 p0 = __floats2half2_rn(acc[i][0], acc[i][1]);
            __half2 p1 = __floats2half2_rn(acc[i][2], acc[i][3]);
            __half2* dstp = (__half2*)&g_h0h[(long long)gm * HH + tx * 4];
            dstp[0] = p0;
            dstp[1] = p1;
        }
        // partial dot for s_src/s_dst, reduced over the 16-lane tx group
        float ps = acc[i][0] * aw0 + acc[i][1] * aw1 + acc[i][2] * aw2 + acc[i][3] * aw3;
        float pd = acc[i][0] * bw0 + acc[i][1] * bw1 + acc[i][2] * bw2 + acc[i][3] * bw3;
#pragma unroll
        for (int o = 8; o > 0; o >>= 1) {
            ps += __shfl_down_sync(0xFFFFFFFFu, ps, o, 16);
            pd += __shfl_down_sync(0xFFFFFFFFu, pd, o, 16);
        }
        if (tx == 0 && gm < NN) {
            g_ssrc[gm] = ps;
            g_sdst[gm] = pd;
        }
    }
    // zero hsum/deg for this block's 128 nodes
    if (tid < 128) {
        int gm = m0 + tid;
        if (gm < NN) {
            g_hsum[gm] = 0.f;
            g_deg[gm] = 0;
        }
    }
}

// ---------------------------------------------------------------------------
// K2: per-edge exp(leaky(logit)); accumulate denominator + degree; compact ids.
// ---------------------------------------------------------------------------
__global__ __launch_bounds__(256) void k_edge1(const void* __restrict__ ei,
                                               const float* __restrict__ ab) {
    int e = blockIdx.x * blockDim.x + threadIdx.x;
    if (e >= EE) return;
    int src = load_idx(ei, 0, e);
    int dst = load_idx(ei, 1, e);
    g_sd[e] = make_int2(src, dst);
    float v = g_ssrc[src] + g_sdst[dst] + ab[0];
    v = (v >= 0.f) ? v : LEAKY * v;
    float h = __expf(v) ;
    // use precise expf to match reference closely
    h = expf(v);
    atomicAdd(&g_hsum[src], h);
    atomicAdd(&g_deg[src], 1);
}

// ---------------------------------------------------------------------------
// K3: exclusive scan of deg
// ---------------------------------------------------------------------------
__global__ __launch_bounds__(SCAN_T) void k_scanA() {
    __shared__ int s[SCAN_T];
    int t = threadIdx.x;
    int i = blockIdx.x * SCAN_T + t;
    int v = (i < NN) ? g_deg[i] : 0;
    s[t] = v;
    __syncthreads();
#pragma unroll
    for (int o = 1; o < SCAN_T; o <<= 1) {
        int x = (t >= o) ? s[t - o] : 0;
        __syncthreads();
        s[t] += x;
        __syncthreads();
    }
    if (i < NN) g_start[i] = s[t] - v;
    if (t == SCAN_T - 1) g_bsum[blockIdx.x] = s[t];
}

__global__ __launch_bounds__(128) void k_scanB() {
    __shared__ int s[128];
    int t = threadIdx.x;
    int v = (t < NBLK) ? g_bsum[t] : 0;
    s[t] = v;
    __syncthreads();
#pragma unroll
    for (int o = 1; o < 128; o <<= 1) {
        int x = (t >= o) ? s[t - o] : 0;
        __syncthreads();
        s[t] += x;
        __syncthreads();
    }
    if (t < NBLK) g_boff[t] = s[t] - v;
}

__global__ __launch_bounds__(256) void k_scanC() {
    int i = blockIdx.x * blockDim.x + threadIdx.x;
    if (i >= NN) return;
    int st = g_start[i] + g_boff[i >> 10];
    g_start[i] = st;
    g_cursor[i] = st;
}

// ---------------------------------------------------------------------------
// K4: scatter edges into CSR slots; recompute alpha; emit alpha.
// ---------------------------------------------------------------------------
__global__ __launch_bounds__(256) void k_scatter(const float* __restrict__ adj,
                                                 const float* __restrict__ ab,
                                                 float* __restrict__ alpha_out) {
    int e = blockIdx.x * blockDim.x + threadIdx.x;
    if (e >= EE) return;
    int2 sd = g_sd[e];
    float v = g_ssrc[sd.x] + g_sdst[sd.y] + ab[0];
    v = (v >= 0.f) ? v : LEAKY * v;
    float alpha = expf(v) / g_hsum[sd.x];
    if (alpha_out) alpha_out[e] = alpha;
    float a = adj[e] * alpha;
    int pos = atomicAdd(&g_cursor[sd.x], 1);
    g_pair[pos] = make_int2(sd.y, __float_as_int(a));
}

// ---------------------------------------------------------------------------
// K5: per-node gather-accumulate over fp16 h0. One warp per node.
// Lane owns columns 2*lane, 2*lane+1 (one half2 = whole row is 1 cache line).
// ---------------------------------------------------------------------------
__global__ __launch_bounds__(256) void k_gather(float* __restrict__ out) {
    int warp = (blockIdx.x * blockDim.x + threadIdx.x) >> 5;
    int lane = threadIdx.x & 31;
    if (warp >= NN) return;
    const __half2* h0 = (const __half2*)g_h0h;
    int beg = g_start[warp];
    int cnt = g_deg[warp];
    float a0 = 0.f, a1 = 0.f;
    for (int b = 0; b < cnt; b += 32) {
        int n = min(32, cnt - b);
        int2 pr = make_int2(0, 0);
        if (lane < n) pr = g_pair[beg + b + lane];
        int j = 0;
        for (; j + 4 <= n; j += 4) {
            int d0 = __shfl_sync(0xFFFFFFFFu, pr.x, j + 0);
            int d1 = __shfl_sync(0xFFFFFFFFu, pr.x, j + 1);
            int d2 = __shfl_sync(0xFFFFFFFFu, pr.x, j + 2);
            int d3 = __shfl_sync(0xFFFFFFFFu, pr.x, j + 3);
            float v0 = __int_as_float(__shfl_sync(0xFFFFFFFFu, pr.y, j + 0));
            float v1 = __int_as_float(__shfl_sync(0xFFFFFFFFu, pr.y, j + 1));
            float v2 = __int_as_float(__shfl_sync(0xFFFFFFFFu, pr.y, j + 2));
            float v3 = __int_as_float(__shfl_sync(0xFFFFFFFFu, pr.y, j + 3));
            __half2 x0 = __ldg(&h0[d0 * 32 + lane]);
            __half2 x1 = __ldg(&h0[d1 * 32 + lane]);
            __half2 x2 = __ldg(&h0[d2 * 32 + lane]);
            __half2 x3 = __ldg(&h0[d3 * 32 + lane]);
            float2 f0 = __half22float2(x0);
            float2 f1 = __half22float2(x1);
            float2 f2 = __half22float2(x2);
            float2 f3 = __half22float2(x3);
            a0 += v0 * f0.x; a1 += v0 * f0.y;
            a0 += v1 * f1.x; a1 += v1 * f1.y;
            a0 += v2 * f2.x; a1 += v2 * f2.y;
            a0 += v3 * f3.x; a1 += v3 * f3.y;
        }
        for (; j < n; j++) {
            int d = __shfl_sync(0xFFFFFFFFu, pr.x, j);
            float v = __int_as_float(__shfl_sync(0xFFFFFFFFu, pr.y, j));
            float2 f = __half22float2(__ldg(&h0[d * 32 + lane]));
            a0 += v * f.x; a1 += v * f.y;
        }
    }
    ((float2*)out)[warp * 32 + lane] = make_float2(a0, a1);
}

// ---------------------------------------------------------------------------
extern "C" void kernel_launch(void* const* d_in, const int* in_sizes, int n_in,
                              void* d_out, int out_size) {
    const float* x    = (const float*)d_in[0];
    const void*  ei   = d_in[1];
    const float* adj  = (const float*)d_in[2];
    const float* fc_w = (const float*)d_in[3];
    const float* a_w  = (const float*)d_in[4];
    const float* a_b  = (const float*)d_in[5];
    float* out = (float*)d_out;
    float* alpha_out = (out_size >= NN * HH + EE) ? (out + NN * HH) : nullptr;

    k_detect<<<1, 32>>>(ei);
    k_gemm<<<(NN + 127) / 128, 256>>>(x, fc_w, a_w);
    k_edge1<<<(EE + 255) / 256, 256>>>(ei, a_b);
    k_scanA<<<NBLK, SCAN_T>>>();
    k_scanB<<<1, 128>>>();
    k_scanC<<<(NN + 255) / 256, 256>>>();
    k_scatter<<<(EE + 255) / 256, 256>>>(adj, a_b, alpha_out);
    k_gather<<<(NN * 32 + 255) / 256, 256>>>(out);
}

// round 5
// speedup vs baseline: 1.3973x; 1.0768x over previous
#include <cuda_runtime.h>
#include <cuda_bf16.h>
#include <cuda_fp16.h>

// GAT layer: N=100000, E=1600000, F=128, H=64.
//   K1 gemm   : h0(fp16) = x @ fc_w^T  via TF32 mma.sync; fused s_src/s_dst
//   K2 edge1  : inline dtype detect; exp(leaky); atomic hsum/deg; compact ids
//   K3 scanA/B/C : exclusive prefix sum of deg (warp-shuffle based)
//   K4 scatter: recompute alpha; pair[pos]=(dst, adj*alpha); alpha_out
//   K5 gather : per-node register accumulation over fp16 h0, no atomics

#define NN 100000
#define EE 1600000
#define FF 128
#define HH 64
#define LEAKY 0.05f
#define SCAN_T 1024
#define NBLK ((NN + SCAN_T - 1) / SCAN_T)   // 98

__device__ __half g_h0h[NN * HH];   // 12.8 MB (fp16 h0)
__device__ float g_ssrc[NN];
__device__ float g_sdst[NN];
__device__ float g_hsum[NN];
__device__ int   g_deg[NN];
__device__ int   g_start[NN];
__device__ int   g_cursor[NN];
__device__ int   g_bsum[NBLK];
__device__ int   g_boff[NBLK];
__device__ int2  g_sd[EE];          // 12.8 MB compact (src,dst)
__device__ int2  g_pair[EE];        // 12.8 MB (dst, adj*alpha)

__device__ __forceinline__ unsigned f2tf32(float f) {
    unsigned r;
    asm("cvt.rna.tf32.f32 %0, %1;" : "=r"(r) : "f"(f));
    return r;
}

// ---------------------------------------------------------------------------
// K1: h0[N,64] = x[N,128] @ W^T via tf32 mma.m16n8k8.
// 256 threads = 8 warps; block tile 128(M) x 64(N); warp tile 16 x 64.
// Fused epilogue: fp16 h0 store + s_src/s_dst dots + hsum/deg zeroing.
// ---------------------------------------------------------------------------
__global__ __launch_bounds__(256) void k_gemm(const float* __restrict__ x,
                                              const float* __restrict__ w,
                                              const float* __restrict__ aw) {
    __shared__ float As[128][33];   // [m][k-chunk], tf32-rounded
    __shared__ float Bs[32][68];    // [k][n],       tf32-rounded

    const int tid  = threadIdx.x;
    const int wrp  = tid >> 5;
    const int lane = tid & 31;
    const int g    = lane >> 2;     // group id 0..7
    const int tg   = lane & 3;      // thread-in-group 0..3
    const int m0   = blockIdx.x * 128;
    const int mw   = wrp * 16;      // warp's row offset in tile

    float acc[8][4];
#pragma unroll
    for (int i = 0; i < 8; i++)
#pragma unroll
        for (int j = 0; j < 4; j++) acc[i][j] = 0.f;

    for (int kc = 0; kc < FF; kc += 32) {
        // load A tile 128x32 (tf32-rounded)
        {
            int k4 = tid & 7;
            int rb = tid >> 3;
#pragma unroll
            for (int r = 0; r < 4; r++) {
                int m = rb + r * 32;
                int gm = m0 + m;
                float4 v = make_float4(0.f, 0.f, 0.f, 0.f);
                if (gm < NN) v = *(const float4*)&x[(long long)gm * FF + kc + k4 * 4];
                As[m][k4 * 4 + 0] = __uint_as_float(f2tf32(v.x));
                As[m][k4 * 4 + 1] = __uint_as_float(f2tf32(v.y));
                As[m][k4 * 4 + 2] = __uint_as_float(f2tf32(v.z));
                As[m][k4 * 4 + 3] = __uint_as_float(f2tf32(v.w));
            }
        }
        // load B tile: W[h][kc..kc+31] -> Bs[k][h] (tf32-rounded)
        {
            int h = tid >> 2;
            int kq = tid & 3;
#pragma unroll
            for (int j = 0; j < 2; j++) {
                int kk = kq * 4 + j * 16;
                float4 v = *(const float4*)&w[h * FF + kc + kk];
                Bs[kk + 0][h] = __uint_as_float(f2tf32(v.x));
                Bs[kk + 1][h] = __uint_as_float(f2tf32(v.y));
                Bs[kk + 2][h] = __uint_as_float(f2tf32(v.z));
                Bs[kk + 3][h] = __uint_as_float(f2tf32(v.w));
            }
        }
        __syncthreads();
#pragma unroll
        for (int ks = 0; ks < 4; ks++) {
            int kk = ks * 8;
            unsigned a0 = __float_as_uint(As[mw + g][kk + tg]);
            unsigned a1 = __float_as_uint(As[mw + g + 8][kk + tg]);
            unsigned a2 = __float_as_uint(As[mw + g][kk + tg + 4]);
            unsigned a3 = __float_as_uint(As[mw + g + 8][kk + tg + 4]);
#pragma unroll
            for (int nt = 0; nt < 8; nt++) {
                int n0 = nt * 8;
                unsigned b0 = __float_as_uint(Bs[kk + tg][n0 + g]);
                unsigned b1 = __float_as_uint(Bs[kk + tg + 4][n0 + g]);
                asm volatile(
                    "mma.sync.aligned.m16n8k8.row.col.f32.tf32.tf32.f32 "
                    "{%0,%1,%2,%3}, {%4,%5,%6,%7}, {%8,%9}, {%0,%1,%2,%3};"
                    : "+f"(acc[nt][0]), "+f"(acc[nt][1]),
                      "+f"(acc[nt][2]), "+f"(acc[nt][3])
                    : "r"(a0), "r"(a1), "r"(a2), "r"(a3), "r"(b0), "r"(b1));
            }
        }
        __syncthreads();
    }

    // Epilogue. Thread owns rows r0 = m0+mw+g, r1 = r0+8;
    // cols nt*8 + 2*tg (+1) for nt in [0,8).
    int r0 = m0 + mw + g;
    int r1 = r0 + 8;
    float ps0 = 0.f, pd0 = 0.f, ps1 = 0.f, pd1 = 0.f;
#pragma unroll
    for (int nt = 0; nt < 8; nt++) {
        int c = nt * 8 + 2 * tg;
        float w0 = __ldg(&aw[c]), w1 = __ldg(&aw[c + 1]);
        float u0 = __ldg(&aw[64 + c]), u1 = __ldg(&aw[64 + c + 1]);
        ps0 += acc[nt][0] * w0 + acc[nt][1] * w1;
        pd0 += acc[nt][0] * u0 + acc[nt][1] * u1;
        ps1 += acc[nt][2] * w0 + acc[nt][3] * w1;
        pd1 += acc[nt][2] * u0 + acc[nt][3] * u1;
        if (r0 < NN)
            *(__half2*)&g_h0h[r0 * HH + c] = __floats2half2_rn(acc[nt][0], acc[nt][1]);
        if (r1 < NN)
            *(__half2*)&g_h0h[r1 * HH + c] = __floats2half2_rn(acc[nt][2], acc[nt][3]);
    }
#pragma unroll
    for (int o = 1; o < 4; o <<= 1) {
        ps0 += __shfl_down_sync(0xFFFFFFFFu, ps0, o, 4);
        pd0 += __shfl_down_sync(0xFFFFFFFFu, pd0, o, 4);
        ps1 += __shfl_down_sync(0xFFFFFFFFu, ps1, o, 4);
        pd1 += __shfl_down_sync(0xFFFFFFFFu, pd1, o, 4);
    }
    if (tg == 0) {
        if (r0 < NN) { g_ssrc[r0] = ps0; g_sdst[r0] = pd0; }
        if (r1 < NN) { g_ssrc[r1] = ps1; g_sdst[r1] = pd1; }
    }
    if (tid < 128) {
        int gm = m0 + tid;
        if (gm < NN) { g_hsum[gm] = 0.f; g_deg[gm] = 0; }
    }
}

// ---------------------------------------------------------------------------
// K2: per-edge exp(leaky(logit)); denominator + degree; compact ids.
// Edge-index dtype (int64 vs int32) detected inline per warp.
// ---------------------------------------------------------------------------
__global__ __launch_bounds__(256) void k_edge1(const void* __restrict__ ei,
                                               const float* __restrict__ ab) {
    int lane = threadIdx.x & 31;
    const long long* p64 = (const long long*)ei;
    long long t0 = p64[lane], t1 = p64[lane + 32];
    bool ok = (t0 >= 0 && t0 < NN && t1 >= 0 && t1 < NN);
    bool is64 = (__ballot_sync(0xFFFFFFFFu, ok) == 0xFFFFFFFFu);

    int e = blockIdx.x * blockDim.x + threadIdx.x;
    if (e >= EE) return;
    int src, dst;
    if (is64) {
        src = (int)p64[e];
        dst = (int)p64[EE + e];
    } else {
        const int* p32 = (const int*)ei;
        src = p32[e];
        dst = p32[EE + e];
    }
    g_sd[e] = make_int2(src, dst);
    float v = g_ssrc[src] + g_sdst[dst] + ab[0];
    v = (v >= 0.f) ? v : LEAKY * v;
    float h = expf(v);
    atomicAdd(&g_hsum[src], h);
    atomicAdd(&g_deg[src], 1);
}

// ---------------------------------------------------------------------------
// K3: exclusive scan of deg (warp-shuffle based)
// ---------------------------------------------------------------------------
__global__ __launch_bounds__(SCAN_T) void k_scanA() {
    __shared__ int ws[32];
    int t = threadIdx.x, lane = t & 31, wid = t >> 5;
    int i = blockIdx.x * SCAN_T + t;
    int v = (i < NN) ? g_deg[i] : 0;
    int incl = v;
#pragma unroll
    for (int o = 1; o < 32; o <<= 1) {
        int y = __shfl_up_sync(0xFFFFFFFFu, incl, o);
        if (lane >= o) incl += y;
    }
    if (lane == 31) ws[wid] = incl;
    __syncthreads();
    if (wid == 0) {
        int s = ws[lane];
        int si = s;
#pragma unroll
        for (int o = 1; o < 32; o <<= 1) {
            int y = __shfl_up_sync(0xFFFFFFFFu, si, o);
            if (lane >= o) si += y;
        }
        ws[lane] = si - s;
    }
    __syncthreads();
    int pref = ws[wid];
    if (i < NN) g_start[i] = pref + incl - v;
    if (t == SCAN_T - 1) g_bsum[blockIdx.x] = pref + incl;
}

__global__ __launch_bounds__(128) void k_scanB() {
    __shared__ int s[128];
    int t = threadIdx.x;
    int v = (t < NBLK) ? g_bsum[t] : 0;
    s[t] = v;
    __syncthreads();
#pragma unroll
    for (int o = 1; o < 128; o <<= 1) {
        int x = (t >= o) ? s[t - o] : 0;
        __syncthreads();
        s[t] += x;
        __syncthreads();
    }
    if (t < NBLK) g_boff[t] = s[t] - v;
}

__global__ __launch_bounds__(256) void k_scanC() {
    int i = blockIdx.x * blockDim.x + threadIdx.x;
    if (i >= NN) return;
    int st = g_start[i] + g_boff[i >> 10];
    g_start[i] = st;
    g_cursor[i] = st;
}

// ---------------------------------------------------------------------------
// K4: scatter edges into CSR slots; recompute alpha; emit alpha.
// ---------------------------------------------------------------------------
__global__ __launch_bounds__(256) void k_scatter(const float* __restrict__ adj,
                                                 const float* __restrict__ ab,
                                                 float* __restrict__ alpha_out) {
    int e = blockIdx.x * blockDim.x + threadIdx.x;
    if (e >= EE) return;
    int2 sd = g_sd[e];
    float v = g_ssrc[sd.x] + g_sdst[sd.y] + ab[0];
    v = (v >= 0.f) ? v : LEAKY * v;
    float alpha = expf(v) / g_hsum[sd.x];
    if (alpha_out) alpha_out[e] = alpha;
    float a = adj[e] * alpha;
    int pos = atomicAdd(&g_cursor[sd.x], 1);
    g_pair[pos] = make_int2(sd.y, __float_as_int(a));
}

// ---------------------------------------------------------------------------
// K5: per-node gather-accumulate over fp16 h0. One warp per node.
// Lane owns columns 2*lane, 2*lane+1 (row = exactly one 128B line).
// ---------------------------------------------------------------------------
__global__ __launch_bounds__(256) void k_gather(float* __restrict__ out) {
    int warp = (blockIdx.x * blockDim.x + threadIdx.x) >> 5;
    int lane = threadIdx.x & 31;
    if (warp >= NN) return;
    const __half2* h0 = (const __half2*)g_h0h;
    int beg = g_start[warp];
    int cnt = g_deg[warp];
    float a0 = 0.f, a1 = 0.f;
    for (int b = 0; b < cnt; b += 32) {
        int n = min(32, cnt - b);
        int2 pr = make_int2(0, 0);
        if (lane < n) pr = g_pair[beg + b + lane];
        int j = 0;
        for (; j + 4 <= n; j += 4) {
            int d0 = __shfl_sync(0xFFFFFFFFu, pr.x, j + 0);
            int d1 = __shfl_sync(0xFFFFFFFFu, pr.x, j + 1);
            int d2 = __shfl_sync(0xFFFFFFFFu, pr.x, j + 2);
            int d3 = __shfl_sync(0xFFFFFFFFu, pr.x, j + 3);
            float v0 = __int_as_float(__shfl_sync(0xFFFFFFFFu, pr.y, j + 0));
            float v1 = __int_as_float(__shfl_sync(0xFFFFFFFFu, pr.y, j + 1));
            float v2 = __int_as_float(__shfl_sync(0xFFFFFFFFu, pr.y, j + 2));
            float v3 = __int_as_float(__shfl_sync(0xFFFFFFFFu, pr.y, j + 3));
            __half2 x0 = __ldg(&h0[d0 * 32 + lane]);
            __half2 x1 = __ldg(&h0[d1 * 32 + lane]);
            __half2 x2 = __ldg(&h0[d2 * 32 + lane]);
            __half2 x3 = __ldg(&h0[d3 * 32 + lane]);
            float2 f0 = __half22float2(x0);
            float2 f1 = __half22float2(x1);
            float2 f2 = __half22float2(x2);
            float2 f3 = __half22float2(x3);
            a0 += v0 * f0.x; a1 += v0 * f0.y;
            a0 += v1 * f1.x; a1 += v1 * f1.y;
            a0 += v2 * f2.x; a1 += v2 * f2.y;
            a0 += v3 * f3.x; a1 += v3 * f3.y;
        }
        for (; j < n; j++) {
            int d = __shfl_sync(0xFFFFFFFFu, pr.x, j);
            float v = __int_as_float(__shfl_sync(0xFFFFFFFFu, pr.y, j));
            float2 f = __half22float2(__ldg(&h0[d * 32 + lane]));
            a0 += v * f.x; a1 += v * f.y;
        }
    }
    ((float2*)out)[warp * 32 + lane] = make_float2(a0, a1);
}

// ---------------------------------------------------------------------------
extern "C" void kernel_launch(void* const* d_in, const int* in_sizes, int n_in,
                              void* d_out, int out_size) {
    const float* x    = (const float*)d_in[0];
    const void*  ei   = d_in[1];
    const float* adj  = (const float*)d_in[2];
    const float* fc_w = (const float*)d_in[3];
    const float* a_w  = (const float*)d_in[4];
    const float* a_b  = (const float*)d_in[5];
    float* out = (float*)d_out;
    float* alpha_out = (out_size >= NN * HH + EE) ? (out + NN * HH) : nullptr;

    k_gemm<<<(NN + 127) / 128, 256>>>(x, fc_w, a_w);
    k_edge1<<<(EE + 255) / 256, 256>>>(ei, a_b);
    k_scanA<<<NBLK, SCAN_T>>>();
    k_scanB<<<1, 128>>>();
    k_scanC<<<(NN + 255) / 256, 256>>>();
    k_scatter<<<(EE + 255) / 256, 256>>>(adj, a_b, alpha_out);
    k_gather<<<(NN * 32 + 255) / 256, 256>>>(out);
}

// round 6
// speedup vs baseline: 1.4558x; 1.0419x over previous
#include <cuda_runtime.h>
#include <cuda_bf16.h>
#include <cuda_fp16.h>

// GAT layer: N=100000, E=1600000, F=128, H=64.
//   K1 gemm   : h0(fp16) = x @ fc_w^T via TF32 mma.sync; fused s_src/s_dst
//   K2 edge1  : inline dtype detect; he=exp(leaky); atomic hsum/deg;
//               compact (src,dst) + he stores
//   K3 scanA  : per-1024-block exclusive scan of deg (int4, warp shuffles)
//   K4 scanC  : add block offsets (in-block reduction over bsum) -> start,cursor
//   K5 scatter: alpha=he/hsum; pair[pos]=(dst, adj*alpha); alpha_out
//   K6 gather : per-node register accumulation over fp16 h0, no atomics

#define NN 100000
#define EE 1600000
#define FF 128
#define HH 64
#define LEAKY 0.05f
#define SCAN_T 1024
#define NBLK ((NN + SCAN_T - 1) / SCAN_T)   // 98

__device__ __half g_h0h[NN * HH];   // 12.8 MB (fp16 h0)
__device__ float g_ssrc[NN];
__device__ float g_sdst[NN];
__device__ float g_hsum[NN];
__device__ float g_he[EE];          // 6.4 MB
__device__ int   g_deg[NN];
__device__ int   g_start[NN];
__device__ int   g_cursor[NN];
__device__ int   g_bsum[NBLK];
__device__ int2  g_sd[EE];          // 12.8 MB compact (src,dst)
__device__ int2  g_pair[EE];        // 12.8 MB (dst, adj*alpha)

__device__ __forceinline__ unsigned f2tf32(float f) {
    unsigned r;
    asm("cvt.rna.tf32.f32 %0, %1;" : "=r"(r) : "f"(f));
    return r;
}

// ---------------------------------------------------------------------------
// K1: h0[N,64] = x[N,128] @ W^T via tf32 mma.m16n8k8.
// 256 threads = 8 warps; block tile 128(M) x 64(N); warp tile 16 x 64.
// ---------------------------------------------------------------------------
__global__ __launch_bounds__(256) void k_gemm(const float* __restrict__ x,
                                              const float* __restrict__ w,
                                              const float* __restrict__ aw) {
    __shared__ float As[128][33];
    __shared__ float Bs[32][68];

    const int tid  = threadIdx.x;
    const int wrp  = tid >> 5;
    const int lane = tid & 31;
    const int g    = lane >> 2;
    const int tg   = lane & 3;
    const int m0   = blockIdx.x * 128;
    const int mw   = wrp * 16;

    float acc[8][4];
#pragma unroll
    for (int i = 0; i < 8; i++)
#pragma unroll
        for (int j = 0; j < 4; j++) acc[i][j] = 0.f;

    for (int kc = 0; kc < FF; kc += 32) {
        {
            int k4 = tid & 7;
            int rb = tid >> 3;
#pragma unroll
            for (int r = 0; r < 4; r++) {
                int m = rb + r * 32;
                int gm = m0 + m;
                float4 v = make_float4(0.f, 0.f, 0.f, 0.f);
                if (gm < NN) v = *(const float4*)&x[(long long)gm * FF + kc + k4 * 4];
                As[m][k4 * 4 + 0] = __uint_as_float(f2tf32(v.x));
                As[m][k4 * 4 + 1] = __uint_as_float(f2tf32(v.y));
                As[m][k4 * 4 + 2] = __uint_as_float(f2tf32(v.z));
                As[m][k4 * 4 + 3] = __uint_as_float(f2tf32(v.w));
            }
        }
        {
            int h = tid >> 2;
            int kq = tid & 3;
#pragma unroll
            for (int j = 0; j < 2; j++) {
                int kk = kq * 4 + j * 16;
                float4 v = *(const float4*)&w[h * FF + kc + kk];
                Bs[kk + 0][h] = __uint_as_float(f2tf32(v.x));
                Bs[kk + 1][h] = __uint_as_float(f2tf32(v.y));
                Bs[kk + 2][h] = __uint_as_float(f2tf32(v.z));
                Bs[kk + 3][h] = __uint_as_float(f2tf32(v.w));
            }
        }
        __syncthreads();
#pragma unroll
        for (int ks = 0; ks < 4; ks++) {
            int kk = ks * 8;
            unsigned a0 = __float_as_uint(As[mw + g][kk + tg]);
            unsigned a1 = __float_as_uint(As[mw + g + 8][kk + tg]);
            unsigned a2 = __float_as_uint(As[mw + g][kk + tg + 4]);
            unsigned a3 = __float_as_uint(As[mw + g + 8][kk + tg + 4]);
#pragma unroll
            for (int nt = 0; nt < 8; nt++) {
                int n0 = nt * 8;
                unsigned b0 = __float_as_uint(Bs[kk + tg][n0 + g]);
                unsigned b1 = __float_as_uint(Bs[kk + tg + 4][n0 + g]);
                asm volatile(
                    "mma.sync.aligned.m16n8k8.row.col.f32.tf32.tf32.f32 "
                    "{%0,%1,%2,%3}, {%4,%5,%6,%7}, {%8,%9}, {%0,%1,%2,%3};"
                    : "+f"(acc[nt][0]), "+f"(acc[nt][1]),
                      "+f"(acc[nt][2]), "+f"(acc[nt][3])
                    : "r"(a0), "r"(a1), "r"(a2), "r"(a3), "r"(b0), "r"(b1));
            }
        }
        __syncthreads();
    }

    int r0 = m0 + mw + g;
    int r1 = r0 + 8;
    float ps0 = 0.f, pd0 = 0.f, ps1 = 0.f, pd1 = 0.f;
#pragma unroll
    for (int nt = 0; nt < 8; nt++) {
        int c = nt * 8 + 2 * tg;
        float w0 = __ldg(&aw[c]), w1 = __ldg(&aw[c + 1]);
        float u0 = __ldg(&aw[64 + c]), u1 = __ldg(&aw[64 + c + 1]);
        ps0 += acc[nt][0] * w0 + acc[nt][1] * w1;
        pd0 += acc[nt][0] * u0 + acc[nt][1] * u1;
        ps1 += acc[nt][2] * w0 + acc[nt][3] * w1;
        pd1 += acc[nt][2] * u0 + acc[nt][3] * u1;
        if (r0 < NN)
            *(__half2*)&g_h0h[r0 * HH + c] = __floats2half2_rn(acc[nt][0], acc[nt][1]);
        if (r1 < NN)
            *(__half2*)&g_h0h[r1 * HH + c] = __floats2half2_rn(acc[nt][2], acc[nt][3]);
    }
#pragma unroll
    for (int o = 1; o < 4; o <<= 1) {
        ps0 += __shfl_down_sync(0xFFFFFFFFu, ps0, o, 4);
        pd0 += __shfl_down_sync(0xFFFFFFFFu, pd0, o, 4);
        ps1 += __shfl_down_sync(0xFFFFFFFFu, ps1, o, 4);
        pd1 += __shfl_down_sync(0xFFFFFFFFu, pd1, o, 4);
    }
    if (tg == 0) {
        if (r0 < NN) { g_ssrc[r0] = ps0; g_sdst[r0] = pd0; }
        if (r1 < NN) { g_ssrc[r1] = ps1; g_sdst[r1] = pd1; }
    }
    if (tid < 128) {
        int gm = m0 + tid;
        if (gm < NN) { g_hsum[gm] = 0.f; g_deg[gm] = 0; }
    }
}

// ---------------------------------------------------------------------------
// K2: per-edge he=exp(leaky(logit)); denominator + degree; compact ids + he.
// ---------------------------------------------------------------------------
__global__ __launch_bounds__(256) void k_edge1(const void* __restrict__ ei,
                                               const float* __restrict__ ab) {
    int lane = threadIdx.x & 31;
    const long long* p64 = (const long long*)ei;
    long long t0 = p64[lane], t1 = p64[lane + 32];
    bool ok = (t0 >= 0 && t0 < NN && t1 >= 0 && t1 < NN);
    bool is64 = (__ballot_sync(0xFFFFFFFFu, ok) == 0xFFFFFFFFu);

    int e = blockIdx.x * blockDim.x + threadIdx.x;
    if (e >= EE) return;
    int src, dst;
    if (is64) {
        src = (int)p64[e];
        dst = (int)p64[EE + e];
    } else {
        const int* p32 = (const int*)ei;
        src = p32[e];
        dst = p32[EE + e];
    }
    g_sd[e] = make_int2(src, dst);
    float v = g_ssrc[src] + g_sdst[dst] + ab[0];
    v = (v >= 0.f) ? v : LEAKY * v;
    float h = expf(v);
    g_he[e] = h;
    atomicAdd(&g_hsum[src], h);
    atomicAdd(&g_deg[src], 1);
}

// ---------------------------------------------------------------------------
// K3: per-block exclusive scan of deg. 256 threads x 4 elements (int4).
// ---------------------------------------------------------------------------
__global__ __launch_bounds__(256) void k_scanA() {
    __shared__ int ws[8];
    int t = threadIdx.x, lane = t & 31, wid = t >> 5;
    int i0 = (blockIdx.x * 256 + t) * 4;
    int4 v = make_int4(0, 0, 0, 0);
    if (i0 + 3 < NN) v = *(const int4*)&g_deg[i0];
    else if (i0 < NN) {
        v.x = g_deg[i0];
        if (i0 + 1 < NN) v.y = g_deg[i0 + 1];
        if (i0 + 2 < NN) v.z = g_deg[i0 + 2];
    }
    int s = v.x + v.y + v.z + v.w;
    int incl = s;
#pragma unroll
    for (int o = 1; o < 32; o <<= 1) {
        int y = __shfl_up_sync(0xFFFFFFFFu, incl, o);
        if (lane >= o) incl += y;
    }
    if (lane == 31) ws[wid] = incl;
    __syncthreads();
    if (wid == 0 && lane < 8) {
        int b = ws[lane];
        int bi = b;
#pragma unroll
        for (int o = 1; o < 8; o <<= 1) {
            int y = __shfl_up_sync(0xFFu, bi, o);
            if (lane >= o) bi += y;
        }
        ws[lane] = bi - b;
    }
    __syncthreads();
    int excl = ws[wid] + incl - s;
    if (i0 + 3 < NN) {
        *(int4*)&g_start[i0] =
            make_int4(excl, excl + v.x, excl + v.x + v.y, excl + v.x + v.y + v.z);
    } else if (i0 < NN) {
        g_start[i0] = excl;
        if (i0 + 1 < NN) g_start[i0 + 1] = excl + v.x;
        if (i0 + 2 < NN) g_start[i0 + 2] = excl + v.x + v.y;
    }
    if (t == 255) g_bsum[blockIdx.x] = excl + s;
}

// ---------------------------------------------------------------------------
// K4: add inter-block offsets. Each 256-node block has one scanA-block id.
// ---------------------------------------------------------------------------
__global__ __launch_bounds__(256) void k_scanC() {
    __shared__ int off_s;
    int ab = blockIdx.x >> 2;   // 256 divides 1024 exactly
    if (threadIdx.x < 32) {
        int s = 0;
        for (int k = threadIdx.x; k < ab; k += 32) s += g_bsum[k];
#pragma unroll
        for (int o = 16; o > 0; o >>= 1)
            s += __shfl_down_sync(0xFFFFFFFFu, s, o);
        if (threadIdx.x == 0) off_s = s;
    }
    __syncthreads();
    int i = blockIdx.x * 256 + threadIdx.x;
    if (i >= NN) return;
    int st = g_start[i] + off_s;
    g_start[i] = st;
    g_cursor[i] = st;
}

// ---------------------------------------------------------------------------
// K5: scatter edges into CSR slots (he read sequentially; 1 random read).
// ---------------------------------------------------------------------------
__global__ __launch_bounds__(256) void k_scatter(const float* __restrict__ adj,
                                                 float* __restrict__ alpha_out) {
    int e = blockIdx.x * blockDim.x + threadIdx.x;
    if (e >= EE) return;
    int2 sd = g_sd[e];
    float alpha = g_he[e] / g_hsum[sd.x];
    if (alpha_out) alpha_out[e] = alpha;
    float a = adj[e] * alpha;
    int pos = atomicAdd(&g_cursor[sd.x], 1);
    g_pair[pos] = make_int2(sd.y, __float_as_int(a));
}

// ---------------------------------------------------------------------------
// K6: per-node gather-accumulate over fp16 h0. One warp per node.
// ---------------------------------------------------------------------------
__global__ __launch_bounds__(256) void k_gather(float* __restrict__ out) {
    int warp = (blockIdx.x * blockDim.x + threadIdx.x) >> 5;
    int lane = threadIdx.x & 31;
    if (warp >= NN) return;
    const __half2* h0 = (const __half2*)g_h0h;
    int beg = g_start[warp];
    int cnt = g_deg[warp];
    float a0 = 0.f, a1 = 0.f;
    for (int b = 0; b < cnt; b += 32) {
        int n = min(32, cnt - b);
        int2 pr = make_int2(0, 0);
        if (lane < n) pr = g_pair[beg + b + lane];
        int j = 0;
        for (; j + 4 <= n; j += 4) {
            int d0 = __shfl_sync(0xFFFFFFFFu, pr.x, j + 0);
            int d1 = __shfl_sync(0xFFFFFFFFu, pr.x, j + 1);
            int d2 = __shfl_sync(0xFFFFFFFFu, pr.x, j + 2);
            int d3 = __shfl_sync(0xFFFFFFFFu, pr.x, j + 3);
            float v0 = __int_as_float(__shfl_sync(0xFFFFFFFFu, pr.y, j + 0));
            float v1 = __int_as_float(__shfl_sync(0xFFFFFFFFu, pr.y, j + 1));
            float v2 = __int_as_float(__shfl_sync(0xFFFFFFFFu, pr.y, j + 2));
            float v3 = __int_as_float(__shfl_sync(0xFFFFFFFFu, pr.y, j + 3));
            __half2 x0 = __ldg(&h0[d0 * 32 + lane]);
            __half2 x1 = __ldg(&h0[d1 * 32 + lane]);
            __half2 x2 = __ldg(&h0[d2 * 32 + lane]);
            __half2 x3 = __ldg(&h0[d3 * 32 + lane]);
            float2 f0 = __half22float2(x0);
            float2 f1 = __half22float2(x1);
            float2 f2 = __half22float2(x2);
            float2 f3 = __half22float2(x3);
            a0 += v0 * f0.x; a1 += v0 * f0.y;
            a0 += v1 * f1.x; a1 += v1 * f1.y;
            a0 += v2 * f2.x; a1 += v2 * f2.y;
            a0 += v3 * f3.x; a1 += v3 * f3.y;
        }
        for (; j < n; j++) {
            int d = __shfl_sync(0xFFFFFFFFu, pr.x, j);
            float v = __int_as_float(__shfl_sync(0xFFFFFFFFu, pr.y, j));
            float2 f = __half22float2(__ldg(&h0[d * 32 + lane]));
            a0 += v * f.x; a1 += v * f.y;
        }
    }
    ((float2*)out)[warp * 32 + lane] = make_float2(a0, a1);
}

// ---------------------------------------------------------------------------
extern "C" void kernel_launch(void* const* d_in, const int* in_sizes, int n_in,
                              void* d_out, int out_size) {
    const float* x    = (const float*)d_in[0];
    const void*  ei   = d_in[1];
    const float* adj  = (const float*)d_in[2];
    const float* fc_w = (const float*)d_in[3];
    const float* a_w  = (const float*)d_in[4];
    const float* a_b  = (const float*)d_in[5];
    float* out = (float*)d_out;
    float* alpha_out = (out_size >= NN * HH + EE) ? (out + NN * HH) : nullptr;

    k_gemm<<<(NN + 127) / 128, 256>>>(x, fc_w, a_w);
    k_edge1<<<(EE + 255) / 256, 256>>>(ei, a_b);
    k_scanA<<<NBLK, 256>>>();
    k_scanC<<<(NN + 255) / 256, 256>>>();
    k_scatter<<<(EE + 255) / 256, 256>>>(adj, alpha_out);
    k_gather<<<(NN * 32 + 255) / 256, 256>>>(out);
}

// round 7
// speedup vs baseline: 1.4779x; 1.0152x over previous
#include <cuda_runtime.h>
#include <cuda_bf16.h>
#include <cuda_fp16.h>

// GAT layer: N=100000, E=1600000, F=128, H=64.
//   K1 gemm   : h0(fp16) = x @ fc_w^T via TF32 mma.sync; fused s_src/s_dst,
//               zeroes {hsum,deg} float2 and scan flags
//   K2 edge1  : 2 edges/thread; he=exp(leaky); ONE red.v2.f32 {he,1} per edge
//   K3 scan   : single-pass exclusive scan (decoupled lookback) -> start,cursor
//   K4 scatter: alpha=he/hsum; pair[pos]=(dst, adj*alpha); alpha_out
//   K5 gather : per-node register accumulation over fp16 h0 (8-way MLP)

#define NN 100000
#define EE 1600000
#define FF 128
#define HH 64
#define LEAKY 0.05f
#define NBLK ((NN + 1023) / 1024)   // 98 scan blocks (1024 nodes each)

__device__ __half g_h0h[NN * HH];   // 12.8 MB (fp16 h0)
__device__ float  g_ssrc[NN];
__device__ float  g_sdst[NN];
__device__ float2 g_hd[NN + 4];     // {hsum, deg}; padded for vector loads
__device__ float  g_he[EE];         // 6.4 MB
__device__ int    g_start[NN + 4];
__device__ int    g_cursor[NN + 4];
__device__ int    g_flag[NBLK];     // 0=none 1=aggregate 2=inclusive
__device__ int    g_aggr[NBLK];
__device__ int    g_incl[NBLK];
__device__ int2   g_sd[EE];         // 12.8 MB compact (src,dst)
__device__ int2   g_pair[EE];       // 12.8 MB (dst, adj*alpha)

__device__ __forceinline__ unsigned f2tf32(float f) {
    unsigned r;
    asm("cvt.rna.tf32.f32 %0, %1;" : "=r"(r) : "f"(f));
    return r;
}

// ---------------------------------------------------------------------------
// K1: h0[N,64] = x[N,128] @ W^T via tf32 mma.m16n8k8.
// ---------------------------------------------------------------------------
__global__ __launch_bounds__(256) void k_gemm(const float* __restrict__ x,
                                              const float* __restrict__ w,
                                              const float* __restrict__ aw) {
    __shared__ float As[128][33];
    __shared__ float Bs[32][68];

    const int tid  = threadIdx.x;
    const int wrp  = tid >> 5;
    const int lane = tid & 31;
    const int g    = lane >> 2;
    const int tg   = lane & 3;
    const int m0   = blockIdx.x * 128;
    const int mw   = wrp * 16;

    // reset scan flags (stream order guarantees this precedes k_scan)
    if (blockIdx.x == 0 && tid < NBLK) g_flag[tid] = 0;

    float acc[8][4];
#pragma unroll
    for (int i = 0; i < 8; i++)
#pragma unroll
        for (int j = 0; j < 4; j++) acc[i][j] = 0.f;

    for (int kc = 0; kc < FF; kc += 32) {
        {
            int k4 = tid & 7;
            int rb = tid >> 3;
#pragma unroll
            for (int r = 0; r < 4; r++) {
                int m = rb + r * 32;
                int gm = m0 + m;
                float4 v = make_float4(0.f, 0.f, 0.f, 0.f);
                if (gm < NN) v = *(const float4*)&x[(long long)gm * FF + kc + k4 * 4];
                As[m][k4 * 4 + 0] = __uint_as_float(f2tf32(v.x));
                As[m][k4 * 4 + 1] = __uint_as_float(f2tf32(v.y));
                As[m][k4 * 4 + 2] = __uint_as_float(f2tf32(v.z));
                As[m][k4 * 4 + 3] = __uint_as_float(f2tf32(v.w));
            }
        }
        {
            int h = tid >> 2;
            int kq = tid & 3;
#pragma unroll
            for (int j = 0; j < 2; j++) {
                int kk = kq * 4 + j * 16;
                float4 v = *(const float4*)&w[h * FF + kc + kk];
                Bs[kk + 0][h] = __uint_as_float(f2tf32(v.x));
                Bs[kk + 1][h] = __uint_as_float(f2tf32(v.y));
                Bs[kk + 2][h] = __uint_as_float(f2tf32(v.z));
                Bs[kk + 3][h] = __uint_as_float(f2tf32(v.w));
            }
        }
        __syncthreads();
#pragma unroll
        for (int ks = 0; ks < 4; ks++) {
            int kk = ks * 8;
            unsigned a0 = __float_as_uint(As[mw + g][kk + tg]);
            unsigned a1 = __float_as_uint(As[mw + g + 8][kk + tg]);
            unsigned a2 = __float_as_uint(As[mw + g][kk + tg + 4]);
            unsigned a3 = __float_as_uint(As[mw + g + 8][kk + tg + 4]);
#pragma unroll
            for (int nt = 0; nt < 8; nt++) {
                int n0 = nt * 8;
                unsigned b0 = __float_as_uint(Bs[kk + tg][n0 + g]);
                unsigned b1 = __float_as_uint(Bs[kk + tg + 4][n0 + g]);
                asm volatile(
                    "mma.sync.aligned.m16n8k8.row.col.f32.tf32.tf32.f32 "
                    "{%0,%1,%2,%3}, {%4,%5,%6,%7}, {%8,%9}, {%0,%1,%2,%3};"
                    : "+f"(acc[nt][0]), "+f"(acc[nt][1]),
                      "+f"(acc[nt][2]), "+f"(acc[nt][3])
                    : "r"(a0), "r"(a1), "r"(a2), "r"(a3), "r"(b0), "r"(b1));
            }
        }
        __syncthreads();
    }

    int r0 = m0 + mw + g;
    int r1 = r0 + 8;
    float ps0 = 0.f, pd0 = 0.f, ps1 = 0.f, pd1 = 0.f;
#pragma unroll
    for (int nt = 0; nt < 8; nt++) {
        int c = nt * 8 + 2 * tg;
        float w0 = __ldg(&aw[c]), w1 = __ldg(&aw[c + 1]);
        float u0 = __ldg(&aw[64 + c]), u1 = __ldg(&aw[64 + c + 1]);
        ps0 += acc[nt][0] * w0 + acc[nt][1] * w1;
        pd0 += acc[nt][0] * u0 + acc[nt][1] * u1;
        ps1 += acc[nt][2] * w0 + acc[nt][3] * w1;
        pd1 += acc[nt][2] * u0 + acc[nt][3] * u1;
        if (r0 < NN)
            *(__half2*)&g_h0h[r0 * HH + c] = __floats2half2_rn(acc[nt][0], acc[nt][1]);
        if (r1 < NN)
            *(__half2*)&g_h0h[r1 * HH + c] = __floats2half2_rn(acc[nt][2], acc[nt][3]);
    }
#pragma unroll
    for (int o = 1; o < 4; o <<= 1) {
        ps0 += __shfl_down_sync(0xFFFFFFFFu, ps0, o, 4);
        pd0 += __shfl_down_sync(0xFFFFFFFFu, pd0, o, 4);
        ps1 += __shfl_down_sync(0xFFFFFFFFu, ps1, o, 4);
        pd1 += __shfl_down_sync(0xFFFFFFFFu, pd1, o, 4);
    }
    if (tg == 0) {
        if (r0 < NN) { g_ssrc[r0] = ps0; g_sdst[r0] = pd0; }
        if (r1 < NN) { g_ssrc[r1] = ps1; g_sdst[r1] = pd1; }
    }
    if (tid < 128) {
        int gm = m0 + tid;
        if (gm < NN) g_hd[gm] = make_float2(0.f, 0.f);
    }
}

// ---------------------------------------------------------------------------
// K2: 2 edges/thread; he=exp(leaky(logit)); one red.v2.f32 {he, 1} per edge.
// ---------------------------------------------------------------------------
__global__ __launch_bounds__(256) void k_edge1(const void* __restrict__ ei,
                                               const float* __restrict__ ab) {
    int lane = threadIdx.x & 31;
    const long long* p64 = (const long long*)ei;
    long long t0 = p64[lane], t1 = p64[lane + 32];
    bool ok = (t0 >= 0 && t0 < NN && t1 >= 0 && t1 < NN);
    bool is64 = (__ballot_sync(0xFFFFFFFFu, ok) == 0xFFFFFFFFu);

    int e = (blockIdx.x * blockDim.x + threadIdx.x) * 2;
    if (e >= EE) return;
    int s0, d0, s1, d1;
    if (is64) {
        longlong2 sp = *(const longlong2*)&p64[e];
        longlong2 dp = *(const longlong2*)&p64[EE + e];
        s0 = (int)sp.x; s1 = (int)sp.y;
        d0 = (int)dp.x; d1 = (int)dp.y;
    } else {
        const int* p32 = (const int*)ei;
        int2 sp = *(const int2*)&p32[e];
        int2 dp = *(const int2*)&p32[EE + e];
        s0 = sp.x; s1 = sp.y;
        d0 = dp.x; d1 = dp.y;
    }
    float bv = __ldg(&ab[0]);
    float v0 = g_ssrc[s0] + g_sdst[d0] + bv;
    float v1 = g_ssrc[s1] + g_sdst[d1] + bv;
    v0 = (v0 >= 0.f) ? v0 : LEAKY * v0;
    v1 = (v1 >= 0.f) ? v1 : LEAKY * v1;
    float h0 = expf(v0);
    float h1 = expf(v1);
    *(int4*)&g_sd[e] = make_int4(s0, d0, s1, d1);
    *(float2*)&g_he[e] = make_float2(h0, h1);
    asm volatile("red.global.add.v2.f32 [%0], {%1, %2};"
                 :: "l"(&g_hd[s0]), "f"(h0), "f"(1.0f) : "memory");
    asm volatile("red.global.add.v2.f32 [%0], {%1, %2};"
                 :: "l"(&g_hd[s1]), "f"(h1), "f"(1.0f) : "memory");
}

// ---------------------------------------------------------------------------
// K3: single-pass exclusive scan of deg with warp-windowed decoupled lookback.
// 98 blocks x 256 threads x 4 nodes. Writes start + cursor.
// ---------------------------------------------------------------------------
__global__ __launch_bounds__(256) void k_scan() {
    __shared__ int ws[8];
    __shared__ int sh_total, sh_off;
    const int b = blockIdx.x, t = threadIdx.x;
    const int lane = t & 31, wid = t >> 5;
    const int i0 = (b * 256 + t) * 4;

    int4 v = make_int4(0, 0, 0, 0);
    if (i0 < NN) {
        const float4* p = (const float4*)&g_hd[i0];   // 2 float2 per float4
        float4 abv = p[0];
        float4 cdv = p[1];
        v.x = (int)abv.y;
        v.y = (i0 + 1 < NN) ? (int)abv.w : 0;
        v.z = (i0 + 2 < NN) ? (int)cdv.y : 0;
        v.w = (i0 + 3 < NN) ? (int)cdv.w : 0;
    }
    int s = v.x + v.y + v.z + v.w;
    int incl = s;
#pragma unroll
    for (int o = 1; o < 32; o <<= 1) {
        int y = __shfl_up_sync(0xFFFFFFFFu, incl, o);
        if (lane >= o) incl += y;
    }
    if (lane == 31) ws[wid] = incl;
    __syncthreads();
    if (wid == 0 && lane < 8) {
        int bv = ws[lane];
        int bi = bv;
#pragma unroll
        for (int o = 1; o < 8; o <<= 1) {
            int y = __shfl_up_sync(0xFFu, bi, o);
            if (lane >= o) bi += y;
        }
        ws[lane] = bi - bv;
        if (lane == 7) sh_total = bi;
    }
    __syncthreads();
    const int total = sh_total;
    const int excl_blk = ws[wid] + incl - s;

    // publish aggregate, then lookback (warp 0)
    if (wid == 0) {
        if (lane == 0) {
            g_aggr[b] = total;
            __threadfence();
            *(volatile int*)&g_flag[b] = 1;
        }
        int run = 0;
        int end = b;
        while (end > 0) {
            int j = end - 1 - lane;
            bool need = (j >= 0);
            int f = 0;
            do {
                if (need) f = *(volatile int*)&g_flag[j];
            } while (__ballot_sync(0xFFFFFFFFu, need && f == 0));
            __threadfence();
            unsigned m2 = __ballot_sync(0xFFFFFFFFu, need && f == 2);
            int val = 0;
            if (m2) {
                int k = __ffs(m2) - 1;
                if (need && lane < k) val = *(volatile int*)&g_aggr[j];
                else if (lane == k)   val = *(volatile int*)&g_incl[j];
                end = 0;
            } else {
                if (need) val = *(volatile int*)&g_aggr[j];
                end = (end >= 32) ? end - 32 : 0;
            }
#pragma unroll
            for (int o = 16; o > 0; o >>= 1)
                val += __shfl_down_sync(0xFFFFFFFFu, val, o);
            run += __shfl_sync(0xFFFFFFFFu, val, 0);
        }
        if (lane == 0) {
            sh_off = run;
            g_incl[b] = run + total;
            __threadfence();
            *(volatile int*)&g_flag[b] = 2;
        }
    }
    __syncthreads();
    const int base = sh_off + excl_blk;
    if (i0 < NN) {
        int4 st = make_int4(base, base + v.x, base + v.x + v.y,
                            base + v.x + v.y + v.z);
        *(int4*)&g_start[i0]  = st;
        *(int4*)&g_cursor[i0] = st;
    }
}

// ---------------------------------------------------------------------------
// K4: scatter edges into CSR slots; alpha = he/hsum; emit alpha.
// ---------------------------------------------------------------------------
__global__ __launch_bounds__(256) void k_scatter(const float* __restrict__ adj,
                                                 float* __restrict__ alpha_out) {
    int e = blockIdx.x * blockDim.x + threadIdx.x;
    if (e >= EE) return;
    int2 sd = g_sd[e];
    float alpha = g_he[e] / g_hd[sd.x].x;
    if (alpha_out) alpha_out[e] = alpha;
    float a = adj[e] * alpha;
    int pos = atomicAdd(&g_cursor[sd.x], 1);
    g_pair[pos] = make_int2(sd.y, __float_as_int(a));
}

// ---------------------------------------------------------------------------
// K5: per-node gather over fp16 h0. One warp per node, 8-deep MLP.
// ---------------------------------------------------------------------------
__global__ __launch_bounds__(256) void k_gather(float* __restrict__ out) {
    int warp = (blockIdx.x * blockDim.x + threadIdx.x) >> 5;
    int lane = threadIdx.x & 31;
    if (warp >= NN) return;
    const __half2* h0 = (const __half2*)g_h0h;
    int beg = g_start[warp];
    int cnt = (int)g_hd[warp].y;
    float a0 = 0.f, a1 = 0.f;
    for (int b = 0; b < cnt; b += 32) {
        int n = min(32, cnt - b);
        int2 pr = make_int2(0, 0);
        if (lane < n) pr = g_pair[beg + b + lane];
        int j = 0;
        for (; j + 8 <= n; j += 8) {
            int   d[8];
            float vv[8];
            __half2 xx[8];
#pragma unroll
            for (int q = 0; q < 8; q++) {
                d[q]  = __shfl_sync(0xFFFFFFFFu, pr.x, j + q);
                vv[q] = __int_as_float(__shfl_sync(0xFFFFFFFFu, pr.y, j + q));
            }
#pragma unroll
            for (int q = 0; q < 8; q++) xx[q] = __ldg(&h0[d[q] * 32 + lane]);
#pragma unroll
            for (int q = 0; q < 8; q++) {
                float2 f = __half22float2(xx[q]);
                a0 += vv[q] * f.x;
                a1 += vv[q] * f.y;
            }
        }
        for (; j < n; j++) {
            int dd = __shfl_sync(0xFFFFFFFFu, pr.x, j);
            float vv = __int_as_float(__shfl_sync(0xFFFFFFFFu, pr.y, j));
            float2 f = __half22float2(__ldg(&h0[dd * 32 + lane]));
            a0 += vv * f.x;
            a1 += vv * f.y;
        }
    }
    ((float2*)out)[warp * 32 + lane] = make_float2(a0, a1);
}

// ---------------------------------------------------------------------------
extern "C" void kernel_launch(void* const* d_in, const int* in_sizes, int n_in,
                              void* d_out, int out_size) {
    const float* x    = (const float*)d_in[0];
    const void*  ei   = d_in[1];
    const float* adj  = (const float*)d_in[2];
    const float* fc_w = (const float*)d_in[3];
    const float* a_w  = (const float*)d_in[4];
    const float* a_b  = (const float*)d_in[5];
    float* out = (float*)d_out;
    float* alpha_out = (out_size >= NN * HH + EE) ? (out + NN * HH) : nullptr;

    k_gemm<<<(NN + 127) / 128, 256>>>(x, fc_w, a_w);
    k_edge1<<<(EE / 2 + 255) / 256, 256>>>(ei, a_b);
    k_scan<<<NBLK, 256>>>();
    k_scatter<<<(EE + 255) / 256, 256>>>(adj, alpha_out);
    k_gather<<<(NN * 32 + 255) / 256, 256>>>(out);
}